// round 2
// baseline (speedup 1.0000x reference)
#include <cuda_runtime.h>
#include <cstdint>

#define D 64

// k1 grids (persistent-ish; rows divisible by 16 for both N=300000 and M=500000)
#define G1X 592
#define G1Y 986
#define G3X 1184
#define G3Y 1184

// Global accumulators / tables (no allocation allowed)
__device__ float g_P[768];                 // [0:384) = Px (6x64), [384:768) = Py
__device__ float g_cx[6 * 64], g_dx[6 * 64];
__device__ float g_cy[6 * 64], g_dy[6 * 64];

struct Ptr6 { const float* p[6]; };
struct K2Args {
    const float* w[12];    // logical order: buy_uu, buy_ui, buy_iu, buy_ii, cart_*, pv_*
    const float* w1[12];   // same order
    const float* edges[3]; // buy, cart, pv
};

// ---------------------------------------------------------------------------
// k0: zero the global accumulator
// ---------------------------------------------------------------------------
__global__ void k0_zero() {
    g_P[threadIdx.x] = 0.0f;
}

// ---------------------------------------------------------------------------
// k1: accumulate p_t = src^T (src w_t) for 6 weight vectors.
// Layout: 16 lanes per row, 4 consecutive floats (float4) per lane.
// ---------------------------------------------------------------------------
__global__ __launch_bounds__(256) void k1_gramvec(
    const float* __restrict__ emb, const int* __restrict__ ids, int n,
    Ptr6 W, int part /* 0 = X, 1 = Y */)
{
    __shared__ float sw[6][64];
    __shared__ float sp[384];
    const int tid = threadIdx.x;

    for (int i = tid; i < 384; i += 256) {
        sw[i >> 6][i & 63] = W.p[i >> 6][i & 63];
        sp[i] = 0.0f;
    }
    __syncthreads();

    const int half = tid >> 4;       // 0..15: row slot within block
    const int lane = tid & 15;       // 0..15: column group
    const int col  = lane * 4;

    float acc[6][4];
#pragma unroll
    for (int t = 0; t < 6; t++) { acc[t][0] = acc[t][1] = acc[t][2] = acc[t][3] = 0.0f; }

    for (int base = blockIdx.x * 16; base < n; base += gridDim.x * 16) {
        const int r  = base + half;
        const int id = ids[r];
        const float4 v = *reinterpret_cast<const float4*>(emb + (size_t)id * D + col);
        const float x0 = 0.1f * v.x, x1 = 0.1f * v.y, x2 = 0.1f * v.z, x3 = 0.1f * v.w;

        float a[6];
#pragma unroll
        for (int t = 0; t < 6; t++) {
            const float4 w4 = *reinterpret_cast<const float4*>(&sw[t][col]);
            a[t] = x0 * w4.x + x1 * w4.y + x2 * w4.z + x3 * w4.w;
        }
        // butterfly reduce within each 16-lane group (offsets < 16 stay in-group)
#pragma unroll
        for (int off = 8; off; off >>= 1)
#pragma unroll
            for (int t = 0; t < 6; t++)
                a[t] += __shfl_xor_sync(0xffffffffu, a[t], off);
#pragma unroll
        for (int t = 0; t < 6; t++) {
            acc[t][0] += a[t] * x0; acc[t][1] += a[t] * x1;
            acc[t][2] += a[t] * x2; acc[t][3] += a[t] * x3;
        }
    }

    // fold lane pairs (l, l+16): same columns, different row stream
#pragma unroll
    for (int t = 0; t < 6; t++)
#pragma unroll
        for (int c = 0; c < 4; c++)
            acc[t][c] += __shfl_xor_sync(0xffffffffu, acc[t][c], 16);

    if ((tid & 16) == 0) {   // lanes 0..15 of each warp
#pragma unroll
        for (int t = 0; t < 6; t++)
#pragma unroll
            for (int c = 0; c < 4; c++)
                atomicAdd(&sp[t * 64 + col + c], acc[t][c]);
    }
    __syncthreads();

    float* gp = g_P + part * 384;
    for (int i = tid; i < 384; i += 256)
        atomicAdd(&gp[i], sp[i]);
}

// ---------------------------------------------------------------------------
// k2: build c/d tables (rank-6 factorization of the output transform),
// copy the 3 passthrough edge vectors. One block, 384 threads.
// ---------------------------------------------------------------------------
__global__ __launch_bounds__(384) void k2_build(K2Args a, float* __restrict__ edge_out)
{
    __shared__ float sP[768];
    const int tid = threadIdx.x;
    sP[tid] = g_P[tid];
    sP[tid + 384] = g_P[tid + 384];
    __syncthreads();

#pragma unroll
    for (int pass = 0; pass < 2; pass++) {
        const int idx  = tid + pass * 384;   // 0..767
        const int term = idx >> 6;           // 0..11
        const int j    = idx & 63;
        const int side = term / 6;           // 0 = x-side, 1 = y-side
        const int t    = term % 6;
        const int b    = t % 3;              // behavior: 0 buy, 1 cart, 2 pv

        const float* p; const float* W1; const float* c;
        if (side == 0) {
            if (t < 3) { p = &sP[b * 64];           W1 = a.w1[4 * b + 0]; c = a.w[4 * b + 0]; } // uu
            else       { p = &sP[384 + b * 64];     W1 = a.w1[4 * b + 1]; c = a.w[4 * b + 1]; } // ui
        } else {
            if (t < 3) { p = &sP[384 + (3 + b) * 64]; W1 = a.w1[4 * b + 3]; c = a.w[4 * b + 3]; } // ii
            else       { p = &sP[(3 + b) * 64];       W1 = a.w1[4 * b + 2]; c = a.w[4 * b + 2]; } // iu
        }
        const float coef = 0.25f * ((b == 0) ? 0.6f : (b == 1) ? 0.3f : 0.1f);

        float u0 = 0.f, u1 = 0.f, u2 = 0.f, u3 = 0.f;
#pragma unroll 4
        for (int k = 0; k < 64; k += 4) {
            u0 += p[k + 0] * W1[(k + 0) * 64 + j];
            u1 += p[k + 1] * W1[(k + 1) * 64 + j];
            u2 += p[k + 2] * W1[(k + 2) * 64 + j];
            u3 += p[k + 3] * W1[(k + 3) * 64 + j];
        }
        const float d = coef * ((u0 + u1) + (u2 + u3));
        if (side == 0) { g_dx[t * 64 + j] = d; g_cx[t * 64 + j] = c[j]; }
        else           { g_dy[t * 64 + j] = d; g_cy[t * 64 + j] = c[j]; }
    }

    if (tid < 192)
        edge_out[tid] = a.edges[tid >> 6][tid & 63];
}

// ---------------------------------------------------------------------------
// k3: out[i] = 0.5 * x_i + sum_t (x_i . c_t) d_t
// ---------------------------------------------------------------------------
__global__ __launch_bounds__(256) void k3_apply(
    const float* __restrict__ emb, const int* __restrict__ ids, int n,
    int side, float* __restrict__ out)
{
    __shared__ float sc[6][64];
    __shared__ float sd[6][64];
    const float* cv = side ? g_cy : g_cx;
    const float* dv = side ? g_dy : g_dx;
    const int tid = threadIdx.x;
    for (int i = tid; i < 384; i += 256) {
        sc[i >> 6][i & 63] = cv[i];
        sd[i >> 6][i & 63] = dv[i];
    }
    __syncthreads();

    const int half = tid >> 4;
    const int lane = tid & 15;
    const int col  = lane * 4;

    for (int base = blockIdx.x * 16; base < n; base += gridDim.x * 16) {
        const int r  = base + half;
        const int id = ids[r];
        const float4 v = *reinterpret_cast<const float4*>(emb + (size_t)id * D + col);
        const float x0 = 0.1f * v.x, x1 = 0.1f * v.y, x2 = 0.1f * v.z, x3 = 0.1f * v.w;

        float a[6];
#pragma unroll
        for (int t = 0; t < 6; t++) {
            const float4 w4 = *reinterpret_cast<const float4*>(&sc[t][col]);
            a[t] = x0 * w4.x + x1 * w4.y + x2 * w4.z + x3 * w4.w;
        }
#pragma unroll
        for (int off = 8; off; off >>= 1)
#pragma unroll
            for (int t = 0; t < 6; t++)
                a[t] += __shfl_xor_sync(0xffffffffu, a[t], off);

        float4 o;
        o.x = 0.5f * x0; o.y = 0.5f * x1; o.z = 0.5f * x2; o.w = 0.5f * x3;
#pragma unroll
        for (int t = 0; t < 6; t++) {
            const float4 d4 = *reinterpret_cast<const float4*>(&sd[t][col]);
            o.x += a[t] * d4.x; o.y += a[t] * d4.y;
            o.z += a[t] * d4.z; o.w += a[t] * d4.w;
        }
        *reinterpret_cast<float4*>(out + (size_t)r * D + col) = o;
    }
}

// ---------------------------------------------------------------------------
extern "C" void kernel_launch(void* const* d_in, const int* in_sizes, int n_in,
                              void* d_out, int out_size)
{
    const int*   uid = (const int*)d_in[0];
    const int*   iid = (const int*)d_in[1];
    const float* ue  = (const float*)d_in[2];
    const float* ie  = (const float*)d_in[3];
    const int nuser = in_sizes[0];
    const int nitem = in_sizes[1];

    // setup_inputs interleaves _w / _w1 per vec:
    //   d_in[4 + 2*v] = _VEC[v]_w,  d_in[5 + 2*v] = _VEC[v]_w1
    // _VEC order: buy_uu(0), buy_ui(1), buy_iu(2), buy_ii(3), cart_...(4..7), pv_...(8..11)
    K2Args ka;
    for (int v = 0; v < 12; v++) {
        ka.w[v]  = (const float*)d_in[4 + 2 * v];
        ka.w1[v] = (const float*)d_in[5 + 2 * v];
    }
    ka.edges[0] = (const float*)d_in[28];
    ka.edges[1] = (const float*)d_in[29];
    ka.edges[2] = (const float*)d_in[30];

    Ptr6 wx, wy;
    for (int b = 0; b < 3; b++) {
        wx.p[b]     = ka.w[4 * b + 0]; // uu  -> Px slots 0..2
        wx.p[3 + b] = ka.w[4 * b + 2]; // iu  -> Px slots 3..5
        wy.p[b]     = ka.w[4 * b + 1]; // ui  -> Py slots 0..2
        wy.p[3 + b] = ka.w[4 * b + 3]; // ii  -> Py slots 3..5
    }

    float* out = (float*)d_out;
    float* edge_out = out + (size_t)(nuser + nitem) * D;

    k0_zero<<<1, 768>>>();
    k1_gramvec<<<G1X, 256>>>(ue, uid, nuser, wx, 0);
    k1_gramvec<<<G1Y, 256>>>(ie, iid, nitem, wy, 1);
    k2_build<<<1, 384>>>(ka, edge_out);
    k3_apply<<<G3X, 256>>>(ue, uid, nuser, 0, out);
    k3_apply<<<G3Y, 256>>>(ie, iid, nitem, 1, out + (size_t)nuser * D);
}